// round 11
// baseline (speedup 1.0000x reference)
#include <cuda_runtime.h>
#include <cuda_bf16.h>
#include <math.h>
#include <stdint.h>

// ---------------- Problem constants ----------------
#define BB 32
#define SS 11
#define NN 4096
#define DD 512
#define MLPD 2048
#define MROWS (BB*NN)          // 131072
#define SROWS (BB*SS)          // 352
#define NCHUNK 16              // n-chunks per batch (4096/256)
#define EPS_LN 1e-5f
#define EPS_ATTN 1e-8f

// ---------------- Scratch (device globals; no allocation allowed) ----------------
__device__ __nv_bfloat16 g_xlnb[MROWS*DD];   // 128 MB normalized inputs (bf16)
__device__ float g_wqk[DD*DD];               // Wq @ Wk^T (fp32)
__device__ float g_vq[DD];                   // qscale * Wq @ bk
__device__ float g_c[SROWS];                 // per-(b,s) logit bias
__device__ float g_qk[SROWS*DD];             // composed query
__device__ float g_attn[BB*NN*16];           // softmax probs, s-padded to 16
__device__ float g_lpart[BB*NCHUNK*16];
__device__ float g_inv[SROWS];               // 1/(sum+eps)
__device__ float g_alpha[SROWS];             // sum/(sum+eps)
__device__ float g_upart[BB*NCHUNK*SS*DD];
__device__ float g_upd[SROWS*DD];            // Tred = inv * (P @ xln)
__device__ float g_updf[SROWS*DD];           // final updates
__device__ float g_gi[SROWS*3*DD];
__device__ float g_gh[SROWS*3*DD];
__device__ float g_stmp[SROWS*DD];
__device__ float g_sA[SROWS*DD];
__device__ float g_sB[SROWS*DD];
__device__ float g_lnb[SROWS*DD];
__device__ float g_h1[SROWS*MLPD];

// ---------------- vq[d] = qscale * sum_j Wq[d][j] * bk[j] (one-time) ----------------
__global__ void __launch_bounds__(128) vq_kernel(
    const float* __restrict__ Wq, const float* __restrict__ bk,
    float qscale, float* __restrict__ vq)
{
    int row = blockIdx.x;
    int t = threadIdx.x;
    float4 w = *(const float4*)(Wq + (size_t)row * DD + t * 4);
    float4 b = *(const float4*)(bk + t * 4);
    float s = w.x * b.x + w.y * b.y + w.z * b.z + w.w * b.w;
    #pragma unroll
    for (int o = 16; o; o >>= 1) s += __shfl_xor_sync(0xffffffffu, s, o);
    __shared__ float sh[4];
    int wi = t >> 5;
    if ((t & 31) == 0) sh[wi] = s;
    __syncthreads();
    if (t == 0) vq[row] = (sh[0] + sh[1] + sh[2] + sh[3]) * qscale;
}

// ---------------- Row LayerNorm -> bf16 out (for inputs) ----------------
__global__ void __launch_bounds__(256) rowln_bf16_kernel(
    const float* __restrict__ X, const float* __restrict__ g,
    const float* __restrict__ b, __nv_bfloat16* __restrict__ out)
{
    int row = blockIdx.x;
    int t = threadIdx.x;
    const float* x = X + (size_t)row * DD;
    float2 v = *(const float2*)(x + 2 * t);
    float s = v.x + v.y;
    float sq = v.x * v.x + v.y * v.y;
    int w = t >> 5, lane = t & 31;
    #pragma unroll
    for (int o = 16; o; o >>= 1) {
        s  += __shfl_xor_sync(0xffffffffu, s, o);
        sq += __shfl_xor_sync(0xffffffffu, sq, o);
    }
    __shared__ float shs[8], shq[8];
    __shared__ float mu_s, rs_s;
    if (lane == 0) { shs[w] = s; shq[w] = sq; }
    __syncthreads();
    if (t == 0) {
        float S = 0.f, Q = 0.f;
        #pragma unroll
        for (int i = 0; i < 8; i++) { S += shs[i]; Q += shq[i]; }
        float mu = S * (1.f / DD);
        float var = Q * (1.f / DD) - mu * mu;
        mu_s = mu;
        rs_s = rsqrtf(var + EPS_LN);
    }
    __syncthreads();
    float mu = mu_s, rs = rs_s;
    float2 gg = *(const float2*)(g + 2 * t);
    float2 bb = *(const float2*)(b + 2 * t);
    float o0 = (v.x - mu) * rs * gg.x + bb.x;
    float o1 = (v.y - mu) * rs * gg.y + bb.y;
    *(__nv_bfloat162*)(out + (size_t)row * DD + 2 * t) = __floats2bfloat162_rn(o0, o1);
}

// ---------------- Row LayerNorm fp32 (slots) + optional dot-with-vq ----------------
__global__ void __launch_bounds__(256) rowln_kernel(
    const float* __restrict__ X, const float* __restrict__ g,
    const float* __restrict__ b, float* __restrict__ out,
    const float* __restrict__ vq, float* __restrict__ cout)
{
    int row = blockIdx.x;
    int t = threadIdx.x;
    const float* x = X + (size_t)row * DD;
    float v0 = x[t], v1 = x[t + 256];
    float s = v0 + v1;
    float sq = v0 * v0 + v1 * v1;
    int w = t >> 5, lane = t & 31;
    #pragma unroll
    for (int o = 16; o; o >>= 1) {
        s  += __shfl_xor_sync(0xffffffffu, s, o);
        sq += __shfl_xor_sync(0xffffffffu, sq, o);
    }
    __shared__ float shs[8], shq[8];
    __shared__ float mu_s, rs_s;
    if (lane == 0) { shs[w] = s; shq[w] = sq; }
    __syncthreads();
    if (t == 0) {
        float S = 0.f, Q = 0.f;
        #pragma unroll
        for (int i = 0; i < 8; i++) { S += shs[i]; Q += shq[i]; }
        float mu = S * (1.f / DD);
        float var = Q * (1.f / DD) - mu * mu;
        mu_s = mu;
        rs_s = rsqrtf(var + EPS_LN);
    }
    __syncthreads();
    float mu = mu_s, rs = rs_s;
    float o0 = (v0 - mu) * rs * g[t]       + b[t];
    float o1 = (v1 - mu) * rs * g[t + 256] + b[t + 256];
    float* o = out + (size_t)row * DD;
    o[t]       = o0;
    o[t + 256] = o1;
    if (vq) {
        float cs = o0 * vq[t] + o1 * vq[t + 256];
        #pragma unroll
        for (int off = 16; off; off >>= 1) cs += __shfl_xor_sync(0xffffffffu, cs, off);
        __shared__ float shc[8];
        if (lane == 0) shc[w] = cs;
        __syncthreads();
        if (t == 0) {
            float C = 0.f;
            #pragma unroll
            for (int i = 0; i < 8; i++) C += shc[i];
            cout[row] = C;
        }
    }
}

// ---------------- Small GEMM: C = scale*(A@op(B)) + rowcoef[m]*bias, opt relu ------
// 16x64x32 tiles, 128 threads, 2x4 per thread. blockIdx.z selects two problem sets.
__global__ void __launch_bounds__(128) gemm_small_kernel(
    const float* __restrict__ A0, const float* __restrict__ A1,
    const float* __restrict__ B0, const float* __restrict__ B1,
    const float* __restrict__ bias0, const float* __restrict__ bias1,
    const float* __restrict__ rc0, const float* __restrict__ rc1,
    float* __restrict__ C0, float* __restrict__ C1,
    int N, int K, int transB, float scale, int relu)
{
    const float* A = blockIdx.z ? A1 : A0;
    const float* Bm = blockIdx.z ? B1 : B0;
    const float* bias = blockIdx.z ? bias1 : bias0;
    const float* rc = blockIdx.z ? rc1 : rc0;
    float* C = blockIdx.z ? C1 : C0;

    __shared__ __align__(16) float As[32][18];
    __shared__ __align__(16) float Bs[32][68];
    int m0 = blockIdx.x * 16, n0 = blockIdx.y * 64;
    int t = threadIdx.x;
    int tx = t & 15, ty = t >> 4;
    float acc[2][4];
    #pragma unroll
    for (int i = 0; i < 2; i++)
        #pragma unroll
        for (int j = 0; j < 4; j++) acc[i][j] = 0.f;

    for (int k0 = 0; k0 < K; k0 += 32) {
        #pragma unroll
        for (int i = 0; i < 4; i++) {
            int idx = t + i * 128;
            int m = idx >> 5, k = idx & 31;
            As[k][m] = A[(size_t)(m0 + m) * K + k0 + k];
        }
        if (!transB) {
            #pragma unroll
            for (int i = 0; i < 16; i++) {
                int idx = t + i * 128;
                int k = idx >> 6, n = idx & 63;
                Bs[k][n] = Bm[(size_t)(k0 + k) * N + n0 + n];
            }
        } else {
            #pragma unroll
            for (int i = 0; i < 16; i++) {
                int idx = t + i * 128;
                int n = idx >> 5, k = idx & 31;
                Bs[k][n] = Bm[(size_t)(n0 + n) * K + k0 + k];
            }
        }
        __syncthreads();
        #pragma unroll
        for (int kk = 0; kk < 32; kk++) {
            float a0 = As[kk][ty * 2], a1 = As[kk][ty * 2 + 1];
            float4 b = *(const float4*)&Bs[kk][tx * 4];
            acc[0][0] = fmaf(a0, b.x, acc[0][0]);
            acc[0][1] = fmaf(a0, b.y, acc[0][1]);
            acc[0][2] = fmaf(a0, b.z, acc[0][2]);
            acc[0][3] = fmaf(a0, b.w, acc[0][3]);
            acc[1][0] = fmaf(a1, b.x, acc[1][0]);
            acc[1][1] = fmaf(a1, b.y, acc[1][1]);
            acc[1][2] = fmaf(a1, b.z, acc[1][2]);
            acc[1][3] = fmaf(a1, b.w, acc[1][3]);
        }
        __syncthreads();
    }
    float4 bvv = make_float4(0.f, 0.f, 0.f, 0.f);
    if (bias) bvv = *(const float4*)(bias + n0 + tx * 4);
    #pragma unroll
    for (int i = 0; i < 2; i++) {
        int m = m0 + ty * 2 + i;
        float coef = rc ? rc[m] : 1.f;
        float4 v;
        v.x = acc[i][0] * scale + bvv.x * coef;
        v.y = acc[i][1] * scale + bvv.y * coef;
        v.z = acc[i][2] * scale + bvv.z * coef;
        v.w = acc[i][3] * scale + bvv.w * coef;
        if (relu) {
            v.x = fmaxf(v.x, 0.f); v.y = fmaxf(v.y, 0.f);
            v.z = fmaxf(v.z, 0.f); v.w = fmaxf(v.w, 0.f);
        }
        *(float4*)(C + (size_t)m * N + n0 + tx * 4) = v;
    }
}

// ------- Tensor-core logits + softmax(over S) + renorm partials -----------------
// logits = qk(bf16) @ xln^T + c[s].  Block = (b, n-chunk of 256).
__global__ void __launch_bounds__(256) logits_softmax_tc_kernel(
    const float* __restrict__ qk, const __nv_bfloat16* __restrict__ Xb,
    const float* __restrict__ cbias,
    float* __restrict__ attn, float* __restrict__ lpart)
{
    __shared__ __align__(16) uint32_t Qs32[16][20];    // [s][k2]
    __shared__ __align__(16) uint32_t Ks32[256][20];   // [n][k2]
    __shared__ float St[16 * 260];                     // logits stash / probs
    __shared__ float c_sh[16];
    int b = blockIdx.x, chunk = blockIdx.y;
    int t = threadIdx.x;
    int warp = t >> 5, lane = t & 31;
    int g = lane >> 2, t4 = lane & 3;
    int n0 = chunk * 256;
    const uint4* kb4 = (const uint4*)(Xb + ((size_t)b * NN + n0) * DD);  // 64 u4/row

    if (t < 16) c_sh[t] = (t < SS) ? cbias[b * SS + t] : 0.f;

    float c[4][4];
    #pragma unroll
    for (int j = 0; j < 4; j++)
        #pragma unroll
        for (int r = 0; r < 4; r++) c[j][r] = 0.f;

    for (int k0 = 0; k0 < DD; k0 += 32) {
        {   // Q: 16 s x 32 k bf16 (convert from fp32) = 256 u32, 1 per thread
            int s = t >> 4, k2 = t & 15;
            float2 f = make_float2(0.f, 0.f);
            if (s < SS) f = *(const float2*)(qk + (size_t)(b * SS + s) * DD + k0 + k2 * 2);
            __nv_bfloat162 h = __floats2bfloat162_rn(f.x, f.y);
            Qs32[s][k2] = *(uint32_t*)&h;
        }
        // X tile: 256 n x 32 k bf16 = 1024 u4, 4 per thread
        #pragma unroll
        for (int i = 0; i < 4; i++) {
            int item = t + i * 256;
            int n = item >> 2, aq = item & 3;
            uint4 v = kb4[(size_t)n * 64 + (k0 >> 3) + aq];
            *(uint4*)&Ks32[n][aq * 4] = v;
        }
        __syncthreads();
        #pragma unroll
        for (int ks = 0; ks < 2; ks++) {
            int kb2 = ks * 8;
            uint32_t a[4];
            a[0] = Qs32[g][kb2 + t4];
            a[1] = Qs32[g + 8][kb2 + t4];
            a[2] = Qs32[g][kb2 + t4 + 4];
            a[3] = Qs32[g + 8][kb2 + t4 + 4];
            #pragma unroll
            for (int j = 0; j < 4; j++) {
                int nb = warp * 32 + j * 8;
                uint32_t b0 = Ks32[nb + g][kb2 + t4];
                uint32_t b1 = Ks32[nb + g][kb2 + t4 + 4];
                asm volatile(
                    "mma.sync.aligned.m16n8k16.row.col.f32.bf16.bf16.f32 "
                    "{%0,%1,%2,%3}, {%4,%5,%6,%7}, {%8,%9}, {%0,%1,%2,%3};\n"
                    : "+f"(c[j][0]), "+f"(c[j][1]), "+f"(c[j][2]), "+f"(c[j][3])
                    : "r"(a[0]), "r"(a[1]), "r"(a[2]), "r"(a[3]),
                      "r"(b0), "r"(b1));
            }
        }
        __syncthreads();
    }

    // stash logits [s][n] (+ per-s bias)
    #pragma unroll
    for (int j = 0; j < 4; j++) {
        int nb = warp * 32 + j * 8;
        St[g * 260 + nb + t4 * 2]           = c[j][0] + c_sh[g];
        St[g * 260 + nb + t4 * 2 + 1]       = c[j][1] + c_sh[g];
        St[(g + 8) * 260 + nb + t4 * 2]     = c[j][2] + c_sh[g + 8];
        St[(g + 8) * 260 + nb + t4 * 2 + 1] = c[j][3] + c_sh[g + 8];
    }
    __syncthreads();

    // per-n softmax over s (each thread owns one n)
    float p[SS];
    {
        int n = t;
        float m = -1e30f;
        #pragma unroll
        for (int s = 0; s < SS; s++) m = fmaxf(m, St[s * 260 + n]);
        float sum = 0.f;
        #pragma unroll
        for (int s = 0; s < SS; s++) { float e = __expf(St[s * 260 + n] - m); p[s] = e; sum += e; }
        float r = 1.f / sum;
        float* ar = attn + ((size_t)b * NN + n0 + n) * 16;
        #pragma unroll
        for (int s = 0; s < SS; s++) { p[s] *= r; ar[s] = p[s]; }
    }
    __syncthreads();
    #pragma unroll
    for (int s = 0; s < SS; s++) St[s * 260 + t] = p[s];
    __syncthreads();

    int w = t >> 5, lane2 = t & 31;
    for (int s = w; s < SS; s += 8) {
        float v = 0.f;
        #pragma unroll
        for (int i = 0; i < 8; i++) v += St[s * 260 + lane2 + i * 32];
        #pragma unroll
        for (int o = 16; o; o >>= 1) v += __shfl_xor_sync(0xffffffffu, v, o);
        if (lane2 == 0) lpart[(b * NCHUNK + chunk) * 16 + s] = v;
    }
}

// ---------------- inv = 1/(sum+eps); alpha = sum*inv ----------------
__global__ void inv_kernel(const float* __restrict__ lpart,
                           float* __restrict__ inv, float* __restrict__ alpha)
{
    int t = threadIdx.x;
    if (t < SROWS) {
        int b = t / SS, s = t % SS;
        float sum = 0.f;
        #pragma unroll
        for (int c = 0; c < NCHUNK; c++) sum += lpart[(b * NCHUNK + c) * 16 + s];
        float iv = 1.f / (sum + EPS_ATTN);
        inv[t] = iv;
        alpha[t] = sum * iv;
    }
}

// ---------------- updates partials: upart = sum_n P[s,n] * xln[n,:] ----------------
__device__ __forceinline__ void fma4(float4& a, float s, float4 v) {
    a.x = fmaf(s, v.x, a.x); a.y = fmaf(s, v.y, a.y);
    a.z = fmaf(s, v.z, a.z); a.w = fmaf(s, v.w, a.w);
}

__global__ void __launch_bounds__(128) updates_kernel(
    const __nv_bfloat16* __restrict__ Xb, const float* __restrict__ attn,
    float* __restrict__ upart)
{
    int b = blockIdx.x, chunk = blockIdx.y, t = threadIdx.x;
    float4 acc[SS];
    #pragma unroll
    for (int s = 0; s < SS; s++) acc[s] = make_float4(0.f, 0.f, 0.f, 0.f);
    const __nv_bfloat16* vb = Xb + (size_t)b * NN * DD;
    const float* pb = attn + (size_t)b * NN * 16;
    int n0 = chunk * 256;
    for (int n = n0; n < n0 + 256; n++) {
        uint2 raw = *(const uint2*)(vb + (size_t)n * DD + t * 4);
        __nv_bfloat162 h0 = *(__nv_bfloat162*)&raw.x;
        __nv_bfloat162 h1 = *(__nv_bfloat162*)&raw.y;
        float2 f0 = __bfloat1622float2(h0);
        float2 f1 = __bfloat1622float2(h1);
        float4 v = make_float4(f0.x, f0.y, f1.x, f1.y);
        const float* pr = pb + (size_t)n * 16;
        float4 p0 = *(const float4*)(pr);
        float4 p1 = *(const float4*)(pr + 4);
        float4 p2 = *(const float4*)(pr + 8);
        fma4(acc[0],  p0.x, v); fma4(acc[1],  p0.y, v);
        fma4(acc[2],  p0.z, v); fma4(acc[3],  p0.w, v);
        fma4(acc[4],  p1.x, v); fma4(acc[5],  p1.y, v);
        fma4(acc[6],  p1.z, v); fma4(acc[7],  p1.w, v);
        fma4(acc[8],  p2.x, v); fma4(acc[9],  p2.y, v);
        fma4(acc[10], p2.z, v);
    }
    #pragma unroll
    for (int s = 0; s < SS; s++)
        *(float4*)(upart + ((size_t)((b * NCHUNK + chunk) * SS + s)) * DD + t * 4) = acc[s];
}

// ---------------- reduce partials + apply inv ----------------
__global__ void __launch_bounds__(128) upd_reduce_kernel(
    const float* __restrict__ upart, const float* __restrict__ inv,
    float* __restrict__ upd)
{
    int row = blockIdx.x;
    int b = row / SS, s = row % SS;
    int t = threadIdx.x;
    float4 acc = make_float4(0.f, 0.f, 0.f, 0.f);
    for (int c = 0; c < NCHUNK; c++) {
        float4 v = *(const float4*)(upart + ((size_t)((b * NCHUNK + c) * SS + s)) * DD + t * 4);
        acc.x += v.x; acc.y += v.y; acc.z += v.z; acc.w += v.w;
    }
    float iv = inv[row];
    acc.x *= iv; acc.y *= iv; acc.z *= iv; acc.w *= iv;
    *(float4*)(upd + (size_t)row * DD + t * 4) = acc;
}

// ---------------- GRU elementwise ----------------
__global__ void __launch_bounds__(256) gru_kernel(
    const float* __restrict__ gi, const float* __restrict__ gh,
    const float* __restrict__ slots, float* __restrict__ out)
{
    int idx = blockIdx.x * 256 + threadIdx.x;
    if (idx >= SROWS * DD) return;
    int row = idx >> 9, d = idx & 511;
    size_t base = (size_t)row * (3 * DD);
    float ir = gi[base + d], iz = gi[base + DD + d], inn = gi[base + 2 * DD + d];
    float hr = gh[base + d], hz = gh[base + DD + d], hn = gh[base + 2 * DD + d];
    float r = 1.f / (1.f + __expf(-(ir + hr)));
    float z = 1.f / (1.f + __expf(-(iz + hz)));
    float nn = tanhf(inn + r * hn);
    out[idx] = (1.f - z) * nn + z * slots[idx];
}

// ---------------- Host orchestration ----------------
extern "C" void kernel_launch(void* const* d_in, const int* in_sizes, int n_in,
                              void* d_out, int out_size)
{
    const float* slots0  = (const float*)d_in[0];
    const float* inputs  = (const float*)d_in[1];
    const float* ln_in_g = (const float*)d_in[2];
    const float* ln_in_b = (const float*)d_in[3];
    const float* Wk      = (const float*)d_in[4];
    const float* bk      = (const float*)d_in[5];
    const float* Wv      = (const float*)d_in[6];
    const float* bv      = (const float*)d_in[7];
    const float* ln_q_g  = (const float*)d_in[8];
    const float* ln_q_b  = (const float*)d_in[9];
    const float* Wq      = (const float*)d_in[10];
    const float* W_ih    = (const float*)d_in[11];
    const float* b_ih    = (const float*)d_in[12];
    const float* W_hh    = (const float*)d_in[13];
    const float* b_hh    = (const float*)d_in[14];
    const float* ln_m_g  = (const float*)d_in[15];
    const float* ln_m_b  = (const float*)d_in[16];
    const float* W1      = (const float*)d_in[17];
    const float* b1      = (const float*)d_in[18];
    const float* W2      = (const float*)d_in[19];
    const float* b2      = (const float*)d_in[20];
    float* out = (float*)d_out;

    __nv_bfloat16 *xlnb;
    float *wqk, *vq, *cb, *qkp, *attn, *lpart, *invp, *alphap, *upart, *upd, *updf;
    float *gi, *gh, *stmp, *sA, *sB, *lnb, *h1;
    cudaGetSymbolAddress((void**)&xlnb,  g_xlnb);
    cudaGetSymbolAddress((void**)&wqk,   g_wqk);
    cudaGetSymbolAddress((void**)&vq,    g_vq);
    cudaGetSymbolAddress((void**)&cb,    g_c);
    cudaGetSymbolAddress((void**)&qkp,   g_qk);
    cudaGetSymbolAddress((void**)&attn,  g_attn);
    cudaGetSymbolAddress((void**)&lpart, g_lpart);
    cudaGetSymbolAddress((void**)&invp,  g_inv);
    cudaGetSymbolAddress((void**)&alphap,g_alpha);
    cudaGetSymbolAddress((void**)&upart, g_upart);
    cudaGetSymbolAddress((void**)&upd,   g_upd);
    cudaGetSymbolAddress((void**)&updf,  g_updf);
    cudaGetSymbolAddress((void**)&gi,    g_gi);
    cudaGetSymbolAddress((void**)&gh,    g_gh);
    cudaGetSymbolAddress((void**)&stmp,  g_stmp);
    cudaGetSymbolAddress((void**)&sA,    g_sA);
    cudaGetSymbolAddress((void**)&sB,    g_sB);
    cudaGetSymbolAddress((void**)&lnb,   g_lnb);
    cudaGetSymbolAddress((void**)&h1,    g_h1);

    const float qscale = 0.044194173824159216f; // 1/sqrt(512)

    // one-time: input LN -> bf16; Wqk = Wq @ Wk^T; vq = qscale * Wq @ bk
    rowln_bf16_kernel<<<MROWS, 256>>>(inputs, ln_in_g, ln_in_b, xlnb);
    gemm_small_kernel<<<dim3(32, 8, 1), 128>>>(
        Wq, Wq, Wk, Wk, nullptr, nullptr, nullptr, nullptr, wqk, wqk,
        DD, DD, 1, 1.f, 0);
    vq_kernel<<<DD, 128>>>(Wq, bk, qscale, vq);

    const float* cur = slots0;
    for (int it = 0; it < 3; it++) {
        // lnb = LN(slots); c[row] = lnb . vq ;  qk = lnb @ Wqk * qscale
        rowln_kernel<<<SROWS, 256>>>(cur, ln_q_g, ln_q_b, lnb, vq, cb);
        gemm_small_kernel<<<dim3(22, 8, 1), 128>>>(
            lnb, lnb, wqk, wqk, nullptr, nullptr, nullptr, nullptr, qkp, qkp,
            DD, DD, 0, qscale, 0);
        // inverted attention on xln directly
        logits_softmax_tc_kernel<<<dim3(BB, NCHUNK), 256>>>(qkp, xlnb, cb, attn, lpart);
        inv_kernel<<<1, 384>>>(lpart, invp, alphap);
        updates_kernel<<<dim3(BB, NCHUNK), 128>>>(xlnb, attn, upart);
        upd_reduce_kernel<<<SROWS, 128>>>(upart, invp, upd);
        // updates = Tred @ Wv + alpha*bv
        gemm_small_kernel<<<dim3(22, 8, 1), 128>>>(
            upd, upd, Wv, Wv, bv, bv, alphap, alphap, updf, updf,
            DD, DD, 0, 1.f, 0);
        // GRU gates (one launch for both)
        gemm_small_kernel<<<dim3(22, 24, 2), 128>>>(
            updf, cur, W_ih, W_hh, b_ih, b_hh, nullptr, nullptr, gi, gh,
            3 * DD, DD, 1, 1.f, 0);
        gru_kernel<<<(SROWS * DD + 255) / 256, 256>>>(gi, gh, cur, stmp);
        // MLP (no residual)
        rowln_kernel<<<SROWS, 256>>>(stmp, ln_m_g, ln_m_b, lnb, nullptr, nullptr);
        gemm_small_kernel<<<dim3(22, 32, 1), 128>>>(
            lnb, lnb, W1, W1, b1, b1, nullptr, nullptr, h1, h1,
            MLPD, DD, 0, 1.f, 1);
        float* nxt = (it == 2) ? out : (it == 0 ? sA : sB);
        gemm_small_kernel<<<dim3(22, 8, 1), 128>>>(
            h1, h1, W2, W2, b2, b2, nullptr, nullptr, nxt, nxt,
            DD, MLPD, 0, 1.f, 0);
        cur = nxt;
    }
}

// round 14
// speedup vs baseline: 1.6155x; 1.6155x over previous
#include <cuda_runtime.h>
#include <cuda_bf16.h>
#include <math.h>
#include <stdint.h>

// ---------------- Problem constants ----------------
#define BB 32
#define SS 11
#define NN 4096
#define DD 512
#define MLPD 2048
#define MROWS (BB*NN)          // 131072
#define SROWS (BB*SS)          // 352
#define NCHUNK 16              // n-chunks per batch (4096/256)
#define EPS_LN 1e-5f
#define EPS_ATTN 1e-8f

// ---------------- Scratch (device globals; no allocation allowed) ----------------
__device__ __nv_bfloat16 g_xlnb[MROWS*DD];   // normalized inputs (bf16)
__device__ __nv_bfloat16 g_kb[MROWS*DD];     // K (bf16)
__device__ __nv_bfloat16 g_vb[MROWS*DD];     // V (bf16)
__device__ __nv_bfloat16 g_wkb[DD*DD];       // Wk transposed [n][k] bf16
__device__ __nv_bfloat16 g_wvb[DD*DD];       // Wv transposed [n][k] bf16
__device__ float g_q[SROWS*DD];
__device__ float g_lpart[BB*NCHUNK*16];
__device__ float g_upart[BB*NCHUNK*SS*DD];
__device__ float g_upd[SROWS*DD];
__device__ float g_gi[SROWS*3*DD];
__device__ float g_gh[SROWS*3*DD];
__device__ float g_stmp[SROWS*DD];
__device__ float g_sA[SROWS*DD];
__device__ float g_sB[SROWS*DD];
__device__ float g_lnb[SROWS*DD];
__device__ float g_h1[SROWS*MLPD];

// ---------------- W transpose + bf16 convert (one-time, tiny) ----------------
__global__ void wtrans_kernel(const float* __restrict__ Wk, const float* __restrict__ Wv,
                              __nv_bfloat16* __restrict__ Ko, __nv_bfloat16* __restrict__ Vo)
{
    __shared__ float tile[32][33];
    const float* src = blockIdx.z ? Wv : Wk;
    __nv_bfloat16* dst = blockIdx.z ? Vo : Ko;
    int k0 = blockIdx.x * 32, n0 = blockIdx.y * 32;
    int tx = threadIdx.x, ty = threadIdx.y;
    tile[ty][tx] = src[(size_t)(k0 + ty) * DD + n0 + tx];
    __syncthreads();
    dst[(size_t)(n0 + ty) * DD + k0 + tx] = __float2bfloat16(tile[tx][ty]);
}

// ---------------- Row LayerNorm -> bf16 out (for inputs) ----------------
__global__ void __launch_bounds__(256) rowln_bf16_kernel(
    const float* __restrict__ X, const float* __restrict__ g,
    const float* __restrict__ b, __nv_bfloat16* __restrict__ out)
{
    int row = blockIdx.x;
    int t = threadIdx.x;
    const float* x = X + (size_t)row * DD;
    float2 v = *(const float2*)(x + 2 * t);
    float s = v.x + v.y;
    float sq = v.x * v.x + v.y * v.y;
    int w = t >> 5, lane = t & 31;
    #pragma unroll
    for (int o = 16; o; o >>= 1) {
        s  += __shfl_xor_sync(0xffffffffu, s, o);
        sq += __shfl_xor_sync(0xffffffffu, sq, o);
    }
    __shared__ float shs[8], shq[8];
    __shared__ float mu_s, rs_s;
    if (lane == 0) { shs[w] = s; shq[w] = sq; }
    __syncthreads();
    if (t == 0) {
        float S = 0.f, Q = 0.f;
        #pragma unroll
        for (int i = 0; i < 8; i++) { S += shs[i]; Q += shq[i]; }
        float mu = S * (1.f / DD);
        float var = Q * (1.f / DD) - mu * mu;
        mu_s = mu;
        rs_s = rsqrtf(var + EPS_LN);
    }
    __syncthreads();
    float mu = mu_s, rs = rs_s;
    float2 gg = *(const float2*)(g + 2 * t);
    float2 bb = *(const float2*)(b + 2 * t);
    float o0 = (v.x - mu) * rs * gg.x + bb.x;
    float o1 = (v.y - mu) * rs * gg.y + bb.y;
    *(__nv_bfloat162*)(out + (size_t)row * DD + 2 * t) = __floats2bfloat162_rn(o0, o1);
}

// ---------------- Row LayerNorm fp32 (slots) ----------------
__global__ void __launch_bounds__(256) rowln_kernel(
    const float* __restrict__ X, const float* __restrict__ g,
    const float* __restrict__ b, float* __restrict__ out)
{
    int row = blockIdx.x;
    int t = threadIdx.x;
    const float* x = X + (size_t)row * DD;
    float v0 = x[t], v1 = x[t + 256];
    float s = v0 + v1;
    float sq = v0 * v0 + v1 * v1;
    int w = t >> 5, lane = t & 31;
    #pragma unroll
    for (int o = 16; o; o >>= 1) {
        s  += __shfl_xor_sync(0xffffffffu, s, o);
        sq += __shfl_xor_sync(0xffffffffu, sq, o);
    }
    __shared__ float shs[8], shq[8];
    __shared__ float mu_s, rs_s;
    if (lane == 0) { shs[w] = s; shq[w] = sq; }
    __syncthreads();
    if (t == 0) {
        float S = 0.f, Q = 0.f;
        #pragma unroll
        for (int i = 0; i < 8; i++) { S += shs[i]; Q += shq[i]; }
        float mu = S * (1.f / DD);
        float var = Q * (1.f / DD) - mu * mu;
        mu_s = mu;
        rs_s = rsqrtf(var + EPS_LN);
    }
    __syncthreads();
    float mu = mu_s, rs = rs_s;
    float* o = out + (size_t)row * DD;
    o[t]       = (v0 - mu) * rs * g[t]       + b[t];
    o[t + 256] = (v1 - mu) * rs * g[t + 256] + b[t + 256];
}

// ---------------- bf16 TC GEMM w/ 3-stage cp.async ring --------------------
// K|V = xlnb @ W^T(+bias), bf16 out. 128x128 tile, BK=32, 256 threads
// (8 warps: 2m x 4n, warp tile 64x32). One __syncthreads per k-iter.
__global__ void __launch_bounds__(256) kv_gemm_bf16_kernel(
    const __nv_bfloat16* __restrict__ A,
    const __nv_bfloat16* __restrict__ Wkb, const __nv_bfloat16* __restrict__ Wvb,
    const float* __restrict__ bk, const float* __restrict__ bv,
    __nv_bfloat16* __restrict__ Kout, __nv_bfloat16* __restrict__ Vout)
{
    __shared__ __align__(16) uint32_t As32[3][128][20];  // [stage][m][k2]
    __shared__ __align__(16) uint32_t Bs32[3][128][20];  // [stage][n][k2]
    int by = blockIdx.x;                 // 0..7 (column block; 0-3 K, 4-7 V)
    int m0 = blockIdx.y * 128;
    const __nv_bfloat16* W; const float* bias; __nv_bfloat16* Dst; int cb;
    if (by < 4) { W = Wkb; bias = bk; Dst = Kout; cb = by * 128; }
    else        { W = Wvb; bias = bv; Dst = Vout; cb = (by - 4) * 128; }

    int t = threadIdx.x;
    int warp = t >> 5, lane = t & 31;
    int wm = (warp & 1) * 64;
    int wn = (warp >> 1) * 32;
    int g = lane >> 2, t4 = lane & 3;

    const uint4* A4 = (const uint4*)A;       // 64 uint4 per 512-col row
    const uint4* W4 = (const uint4*)W;

    float c[4][4][4];
    #pragma unroll
    for (int i = 0; i < 4; i++)
        #pragma unroll
        for (int j = 0; j < 4; j++)
            #pragma unroll
            for (int r = 0; r < 4; r++) c[i][j][r] = 0.f;

#define KV_LOAD(st, kk0) do {                                                   \
        _Pragma("unroll")                                                       \
        for (int i = 0; i < 2; i++) {                                           \
            int item = t + i * 256;                                             \
            int rm = item >> 2, aq = item & 3;                                  \
            const uint4* ga = A4 + (size_t)(m0 + rm) * 64 + ((kk0) >> 3) + aq;  \
            uint32_t sa = (uint32_t)__cvta_generic_to_shared(&As32[st][rm][aq*4]);\
            asm volatile("cp.async.cg.shared.global [%0], [%1], 16;\n"          \
                         :: "r"(sa), "l"(ga));                                  \
            const uint4* gb = W4 + (size_t)(cb + rm) * 64 + ((kk0) >> 3) + aq;  \
            uint32_t sb = (uint32_t)__cvta_generic_to_shared(&Bs32[st][rm][aq*4]);\
            asm volatile("cp.async.cg.shared.global [%0], [%1], 16;\n"          \
                         :: "r"(sb), "l"(gb));                                  \
        }                                                                       \
    } while (0)

    KV_LOAD(0, 0);
    asm volatile("cp.async.commit_group;\n");
    KV_LOAD(1, 32);
    asm volatile("cp.async.commit_group;\n");

    #pragma unroll 1
    for (int it = 0; it < 16; it++) {
        int st = it % 3;
        if (it < 15) asm volatile("cp.async.wait_group 1;\n");
        else         asm volatile("cp.async.wait_group 0;\n");
        __syncthreads();
        // prefetch stage it+2 (safe: sync above guarantees iter it-1 compute done)
        if (it + 2 < 16) {
            int pst = (it + 2) % 3;
            KV_LOAD(pst, (it + 2) * 32);
            asm volatile("cp.async.commit_group;\n");
        }

        #pragma unroll
        for (int ks = 0; ks < 2; ks++) {
            int kb2 = ks * 8;
            uint32_t a[4][4], bf[4][2];
            #pragma unroll
            for (int i = 0; i < 4; i++) {
                int mb = wm + i * 16;
                a[i][0] = As32[st][mb + g][kb2 + t4];
                a[i][1] = As32[st][mb + g + 8][kb2 + t4];
                a[i][2] = As32[st][mb + g][kb2 + t4 + 4];
                a[i][3] = As32[st][mb + g + 8][kb2 + t4 + 4];
            }
            #pragma unroll
            for (int j = 0; j < 4; j++) {
                int nb = wn + j * 8;
                bf[j][0] = Bs32[st][nb + g][kb2 + t4];
                bf[j][1] = Bs32[st][nb + g][kb2 + t4 + 4];
            }
            #pragma unroll
            for (int i = 0; i < 4; i++)
                #pragma unroll
                for (int j = 0; j < 4; j++) {
                    asm volatile(
                        "mma.sync.aligned.m16n8k16.row.col.f32.bf16.bf16.f32 "
                        "{%0,%1,%2,%3}, {%4,%5,%6,%7}, {%8,%9}, {%0,%1,%2,%3};\n"
                        : "+f"(c[i][j][0]), "+f"(c[i][j][1]),
                          "+f"(c[i][j][2]), "+f"(c[i][j][3])
                        : "r"(a[i][0]), "r"(a[i][1]), "r"(a[i][2]), "r"(a[i][3]),
                          "r"(bf[j][0]), "r"(bf[j][1]));
                }
        }
    }
#undef KV_LOAD

    // epilogue: bias add, convert bf16x2, store. Dst row stride 512 bf16 = 256 u32.
    uint32_t* D32 = (uint32_t*)Dst;
    #pragma unroll
    for (int i = 0; i < 4; i++) {
        int row = m0 + wm + i * 16 + g;
        #pragma unroll
        for (int j = 0; j < 4; j++) {
            int col = wn + j * 8 + t4 * 2;           // within 128-wide tile
            float bx = bias[cb + col], by2 = bias[cb + col + 1];
            int c2 = ((cb + col) >> 1);
            __nv_bfloat162 v0 = __floats2bfloat162_rn(c[i][j][0] + bx, c[i][j][1] + by2);
            __nv_bfloat162 v1 = __floats2bfloat162_rn(c[i][j][2] + bx, c[i][j][3] + by2);
            D32[(size_t)row * 256 + c2] = *(uint32_t*)&v0;
            D32[(size_t)(row + 8) * 256 + c2] = *(uint32_t*)&v1;
        }
    }
}

// ---------------- Small GEMM: C = scale*(A@op(B)) + bias, opt relu ----------------
// 16x64x32 tiles, 128 threads, 2x4 per thread. blockIdx.z selects two problem sets.
__global__ void __launch_bounds__(128) gemm_small_kernel(
    const float* __restrict__ A0, const float* __restrict__ A1,
    const float* __restrict__ B0, const float* __restrict__ B1,
    const float* __restrict__ bias0, const float* __restrict__ bias1,
    float* __restrict__ C0, float* __restrict__ C1,
    int N, int K, int transB, float scale, int relu)
{
    const float* A = blockIdx.z ? A1 : A0;
    const float* Bm = blockIdx.z ? B1 : B0;
    const float* bias = blockIdx.z ? bias1 : bias0;
    float* C = blockIdx.z ? C1 : C0;

    __shared__ __align__(16) float As[32][18];
    __shared__ __align__(16) float Bs[32][68];
    int m0 = blockIdx.x * 16, n0 = blockIdx.y * 64;
    int t = threadIdx.x;
    int tx = t & 15, ty = t >> 4;
    float acc[2][4];
    #pragma unroll
    for (int i = 0; i < 2; i++)
        #pragma unroll
        for (int j = 0; j < 4; j++) acc[i][j] = 0.f;

    for (int k0 = 0; k0 < K; k0 += 32) {
        #pragma unroll
        for (int i = 0; i < 4; i++) {
            int idx = t + i * 128;
            int m = idx >> 5, k = idx & 31;
            As[k][m] = A[(size_t)(m0 + m) * K + k0 + k];
        }
        if (!transB) {
            #pragma unroll
            for (int i = 0; i < 16; i++) {
                int idx = t + i * 128;
                int k = idx >> 6, n = idx & 63;
                Bs[k][n] = Bm[(size_t)(k0 + k) * N + n0 + n];
            }
        } else {
            #pragma unroll
            for (int i = 0; i < 16; i++) {
                int idx = t + i * 128;
                int n = idx >> 5, k = idx & 31;
                Bs[k][n] = Bm[(size_t)(n0 + n) * K + k0 + k];
            }
        }
        __syncthreads();
        #pragma unroll
        for (int kk = 0; kk < 32; kk++) {
            float a0 = As[kk][ty * 2], a1 = As[kk][ty * 2 + 1];
            float4 b = *(const float4*)&Bs[kk][tx * 4];
            acc[0][0] = fmaf(a0, b.x, acc[0][0]);
            acc[0][1] = fmaf(a0, b.y, acc[0][1]);
            acc[0][2] = fmaf(a0, b.z, acc[0][2]);
            acc[0][3] = fmaf(a0, b.w, acc[0][3]);
            acc[1][0] = fmaf(a1, b.x, acc[1][0]);
            acc[1][1] = fmaf(a1, b.y, acc[1][1]);
            acc[1][2] = fmaf(a1, b.z, acc[1][2]);
            acc[1][3] = fmaf(a1, b.w, acc[1][3]);
        }
        __syncthreads();
    }
    float4 bvv = make_float4(0.f, 0.f, 0.f, 0.f);
    if (bias) bvv = *(const float4*)(bias + n0 + tx * 4);
    #pragma unroll
    for (int i = 0; i < 2; i++) {
        int m = m0 + ty * 2 + i;
        float4 v;
        v.x = acc[i][0] * scale + bvv.x;
        v.y = acc[i][1] * scale + bvv.y;
        v.z = acc[i][2] * scale + bvv.z;
        v.w = acc[i][3] * scale + bvv.w;
        if (relu) {
            v.x = fmaxf(v.x, 0.f); v.y = fmaxf(v.y, 0.f);
            v.z = fmaxf(v.z, 0.f); v.w = fmaxf(v.w, 0.f);
        }
        *(float4*)(C + (size_t)m * N + n0 + tx * 4) = v;
    }
}

// ------- Fused attention: TC logits + softmax(over S) + P@V, one kernel ---------
// Block = (b, n-chunk of 256), 256 threads. Probs stay fp32 (numerics == R9).
__global__ void __launch_bounds__(256) attn_fused_kernel(
    const float* __restrict__ q, const __nv_bfloat16* __restrict__ Kb,
    const __nv_bfloat16* __restrict__ Vb,
    float* __restrict__ lpart, float* __restrict__ upart)
{
    __shared__ __align__(16) uint32_t Qs32[16][20];    // [s][k2]
    __shared__ __align__(16) uint32_t Ks32[256][20];   // [n][k2]
    __shared__ __align__(16) float StT[256][20];       // [n][s] logits -> probs
    __shared__ float wsum[8][12];
    int b = blockIdx.x, chunk = blockIdx.y;
    int t = threadIdx.x;
    int warp = t >> 5, lane = t & 31;
    int g = lane >> 2, t4 = lane & 3;
    int n0 = chunk * 256;
    const uint4* kb4 = (const uint4*)(Kb + ((size_t)b * NN + n0) * DD);  // 64 u4/row

    float c[4][4];
    #pragma unroll
    for (int j = 0; j < 4; j++)
        #pragma unroll
        for (int r = 0; r < 4; r++) c[j][r] = 0.f;

    for (int k0 = 0; k0 < DD; k0 += 32) {
        {   // Q: 16 s x 32 k bf16 (convert from fp32) = 256 u32, 1 per thread
            int s = t >> 4, k2 = t & 15;
            float2 f = make_float2(0.f, 0.f);
            if (s < SS) f = *(const float2*)(q + (size_t)(b * SS + s) * DD + k0 + k2 * 2);
            __nv_bfloat162 h = __floats2bfloat162_rn(f.x, f.y);
            Qs32[s][k2] = *(uint32_t*)&h;
        }
        // K tile: 256 n x 32 k bf16 = 1024 u4, 4 per thread
        #pragma unroll
        for (int i = 0; i < 4; i++) {
            int item = t + i * 256;
            int n = item >> 2, aq = item & 3;
            uint4 v = kb4[(size_t)n * 64 + (k0 >> 3) + aq];
            *(uint4*)&Ks32[n][aq * 4] = v;
        }
        __syncthreads();
        #pragma unroll
        for (int ks = 0; ks < 2; ks++) {
            int kb2 = ks * 8;
            uint32_t a[4];
            a[0] = Qs32[g][kb2 + t4];
            a[1] = Qs32[g + 8][kb2 + t4];
            a[2] = Qs32[g][kb2 + t4 + 4];
            a[3] = Qs32[g + 8][kb2 + t4 + 4];
            #pragma unroll
            for (int j = 0; j < 4; j++) {
                int nb = warp * 32 + j * 8;
                uint32_t b0 = Ks32[nb + g][kb2 + t4];
                uint32_t b1 = Ks32[nb + g][kb2 + t4 + 4];
                asm volatile(
                    "mma.sync.aligned.m16n8k16.row.col.f32.bf16.bf16.f32 "
                    "{%0,%1,%2,%3}, {%4,%5,%6,%7}, {%8,%9}, {%0,%1,%2,%3};\n"
                    : "+f"(c[j][0]), "+f"(c[j][1]), "+f"(c[j][2]), "+f"(c[j][3])
                    : "r"(a[0]), "r"(a[1]), "r"(a[2]), "r"(a[3]),
                      "r"(b0), "r"(b1));
            }
        }
        __syncthreads();
    }

    // stash logits transposed [n][s] (conflict-free: bank = (40*t4+g)%32 is a permutation)
    #pragma unroll
    for (int j = 0; j < 4; j++) {
        int nn = warp * 32 + j * 8 + t4 * 2;
        StT[nn][g]         = c[j][0];
        StT[nn + 1][g]     = c[j][1];
        StT[nn][g + 8]     = c[j][2];
        StT[nn + 1][g + 8] = c[j][3];
    }
    __syncthreads();

    // per-n softmax over s (thread t owns n = t); probs stay fp32
    float p[SS];
    {
        float4 l0 = *(const float4*)&StT[t][0];
        float4 l1 = *(const float4*)&StT[t][4];
        float4 l2 = *(const float4*)&StT[t][8];
        p[0]=l0.x; p[1]=l0.y; p[2]=l0.z; p[3]=l0.w;
        p[4]=l1.x; p[5]=l1.y; p[6]=l1.z; p[7]=l1.w;
        p[8]=l2.x; p[9]=l2.y; p[10]=l2.z;
        float m = -1e30f;
        #pragma unroll
        for (int s = 0; s < SS; s++) m = fmaxf(m, p[s]);
        float sum = 0.f;
        #pragma unroll
        for (int s = 0; s < SS; s++) { p[s] = __expf(p[s] - m); sum += p[s]; }
        float r = 1.f / sum;
        #pragma unroll
        for (int s = 0; s < SS; s++) p[s] *= r;
    }
    // renorm partials: warp-reduce each p[s] over the 32 n's, then across warps
    #pragma unroll
    for (int s = 0; s < SS; s++) {
        float v = p[s];
        #pragma unroll
        for (int o = 16; o; o >>= 1) v += __shfl_xor_sync(0xffffffffu, v, o);
        if (lane == 0) wsum[warp][s] = v;
    }
    // write probs back (slot s=11 garbage, never read)
    *(float4*)&StT[t][0] = make_float4(p[0], p[1], p[2], p[3]);
    *(float4*)&StT[t][4] = make_float4(p[4], p[5], p[6], p[7]);
    *(float4*)&StT[t][8] = make_float4(p[8], p[9], p[10], 0.f);
    __syncthreads();
    if (t < SS) {
        float v = 0.f;
        #pragma unroll
        for (int w = 0; w < 8; w++) v += wsum[w][t];
        lpart[(b * NCHUNK + chunk) * 16 + t] = v;
    }

    // pass 2: upart[s][d] = sum_n P[s][n] * V[n][d]; thread owns d = 2t, 2t+1
    const __nv_bfloat16* vb = Vb + (size_t)b * NN * DD;
    float acc[SS][2];
    #pragma unroll
    for (int s = 0; s < SS; s++) { acc[s][0] = 0.f; acc[s][1] = 0.f; }
    for (int n = 0; n < 256; n++) {
        uint32_t raw = *(const uint32_t*)(vb + (size_t)(n0 + n) * DD + 2 * t);
        float2 v = __bfloat1622float2(*(__nv_bfloat162*)&raw);
        float4 p0 = *(const float4*)&StT[n][0];
        float4 p1 = *(const float4*)&StT[n][4];
        float4 p2 = *(const float4*)&StT[n][8];
        acc[0][0]  = fmaf(p0.x, v.x, acc[0][0]);  acc[0][1]  = fmaf(p0.x, v.y, acc[0][1]);
        acc[1][0]  = fmaf(p0.y, v.x, acc[1][0]);  acc[1][1]  = fmaf(p0.y, v.y, acc[1][1]);
        acc[2][0]  = fmaf(p0.z, v.x, acc[2][0]);  acc[2][1]  = fmaf(p0.z, v.y, acc[2][1]);
        acc[3][0]  = fmaf(p0.w, v.x, acc[3][0]);  acc[3][1]  = fmaf(p0.w, v.y, acc[3][1]);
        acc[4][0]  = fmaf(p1.x, v.x, acc[4][0]);  acc[4][1]  = fmaf(p1.x, v.y, acc[4][1]);
        acc[5][0]  = fmaf(p1.y, v.x, acc[5][0]);  acc[5][1]  = fmaf(p1.y, v.y, acc[5][1]);
        acc[6][0]  = fmaf(p1.z, v.x, acc[6][0]);  acc[6][1]  = fmaf(p1.z, v.y, acc[6][1]);
        acc[7][0]  = fmaf(p1.w, v.x, acc[7][0]);  acc[7][1]  = fmaf(p1.w, v.y, acc[7][1]);
        acc[8][0]  = fmaf(p2.x, v.x, acc[8][0]);  acc[8][1]  = fmaf(p2.x, v.y, acc[8][1]);
        acc[9][0]  = fmaf(p2.y, v.x, acc[9][0]);  acc[9][1]  = fmaf(p2.y, v.y, acc[9][1]);
        acc[10][0] = fmaf(p2.z, v.x, acc[10][0]); acc[10][1] = fmaf(p2.z, v.y, acc[10][1]);
    }
    #pragma unroll
    for (int s = 0; s < SS; s++) {
        float2 o = make_float2(acc[s][0], acc[s][1]);
        *(float2*)(upart + ((size_t)((b * NCHUNK + chunk) * SS + s)) * DD + 2 * t) = o;
    }
}

// ---------------- reduce partials + compute inv inline + apply ----------------
__global__ void __launch_bounds__(128) upd_reduce_kernel(
    const float* __restrict__ upart, const float* __restrict__ lpart,
    float* __restrict__ upd)
{
    int row = blockIdx.x;               // 0..351
    int b = row / SS, s = row % SS;
    int t = threadIdx.x;
    float sum = 0.f;
    #pragma unroll
    for (int c = 0; c < NCHUNK; c++) sum += lpart[(b * NCHUNK + c) * 16 + s];
    float iv = 1.f / (sum + EPS_ATTN);
    float4 acc = make_float4(0.f, 0.f, 0.f, 0.f);
    for (int c = 0; c < NCHUNK; c++) {
        float4 v = *(const float4*)(upart + ((size_t)((b * NCHUNK + c) * SS + s)) * DD + t * 4);
        acc.x += v.x; acc.y += v.y; acc.z += v.z; acc.w += v.w;
    }
    acc.x *= iv; acc.y *= iv; acc.z *= iv; acc.w *= iv;
    *(float4*)(upd + (size_t)row * DD + t * 4) = acc;
}

// ---------------- GRU elementwise ----------------
__global__ void __launch_bounds__(256) gru_kernel(
    const float* __restrict__ gi, const float* __restrict__ gh,
    const float* __restrict__ slots, float* __restrict__ out)
{
    int idx = blockIdx.x * 256 + threadIdx.x;
    if (idx >= SROWS * DD) return;
    int row = idx >> 9, d = idx & 511;
    size_t base = (size_t)row * (3 * DD);
    float ir = gi[base + d], iz = gi[base + DD + d], inn = gi[base + 2 * DD + d];
    float hr = gh[base + d], hz = gh[base + DD + d], hn = gh[base + 2 * DD + d];
    float r = 1.f / (1.f + __expf(-(ir + hr)));
    float z = 1.f / (1.f + __expf(-(iz + hz)));
    float nn = tanhf(inn + r * hn);
    out[idx] = (1.f - z) * nn + z * slots[idx];
}

// ---------------- Host orchestration ----------------
extern "C" void kernel_launch(void* const* d_in, const int* in_sizes, int n_in,
                              void* d_out, int out_size)
{
    const float* slots0  = (const float*)d_in[0];
    const float* inputs  = (const float*)d_in[1];
    const float* ln_in_g = (const float*)d_in[2];
    const float* ln_in_b = (const float*)d_in[3];
    const float* Wk      = (const float*)d_in[4];
    const float* bk      = (const float*)d_in[5];
    const float* Wv      = (const float*)d_in[6];
    const float* bv      = (const float*)d_in[7];
    const float* ln_q_g  = (const float*)d_in[8];
    const float* ln_q_b  = (const float*)d_in[9];
    const float* Wq      = (const float*)d_in[10];
    const float* W_ih    = (const float*)d_in[11];
    const float* b_ih    = (const float*)d_in[12];
    const float* W_hh    = (const float*)d_in[13];
    const float* b_hh    = (const float*)d_in[14];
    const float* ln_m_g  = (const float*)d_in[15];
    const float* ln_m_b  = (const float*)d_in[16];
    const float* W1      = (const float*)d_in[17];
    const float* b1      = (const float*)d_in[18];
    const float* W2      = (const float*)d_in[19];
    const float* b2      = (const float*)d_in[20];
    float* out = (float*)d_out;

    __nv_bfloat16 *xlnb, *kb, *vb2, *wkb, *wvb;
    float *qp, *lpart, *upart, *upd, *gi, *gh;
    float *stmp, *sA, *sB, *lnb, *h1;
    cudaGetSymbolAddress((void**)&xlnb, g_xlnb);
    cudaGetSymbolAddress((void**)&kb,   g_kb);
    cudaGetSymbolAddress((void**)&vb2,  g_vb);
    cudaGetSymbolAddress((void**)&wkb,  g_wkb);
    cudaGetSymbolAddress((void**)&wvb,  g_wvb);
    cudaGetSymbolAddress((void**)&qp,   g_q);
    cudaGetSymbolAddress((void**)&lpart,g_lpart);
    cudaGetSymbolAddress((void**)&upart,g_upart);
    cudaGetSymbolAddress((void**)&upd,  g_upd);
    cudaGetSymbolAddress((void**)&gi,   g_gi);
    cudaGetSymbolAddress((void**)&gh,   g_gh);
    cudaGetSymbolAddress((void**)&stmp, g_stmp);
    cudaGetSymbolAddress((void**)&sA,   g_sA);
    cudaGetSymbolAddress((void**)&sB,   g_sB);
    cudaGetSymbolAddress((void**)&lnb,  g_lnb);
    cudaGetSymbolAddress((void**)&h1,   g_h1);

    const float qscale = 0.044194173824159216f; // 1/sqrt(512)

    // one-time: W transpose->bf16, input LN->bf16, kv GEMM (bf16 TC + 3-stage cp.async)
    wtrans_kernel<<<dim3(16, 16, 2), dim3(32, 32)>>>(Wk, Wv, wkb, wvb);
    rowln_bf16_kernel<<<MROWS, 256>>>(inputs, ln_in_g, ln_in_b, xlnb);
    kv_gemm_bf16_kernel<<<dim3(8, MROWS / 128), 256>>>(xlnb, wkb, wvb, bk, bv, kb, vb2);

    const float* cur = slots0;
    for (int it = 0; it < 3; it++) {
        // q = LN(slots) @ Wq * scale
        rowln_kernel<<<SROWS, 256>>>(cur, ln_q_g, ln_q_b, lnb);
        gemm_small_kernel<<<dim3(22, 8, 1), 128>>>(
            lnb, lnb, Wq, Wq, nullptr, nullptr, qp, qp,
            DD, DD, 0, qscale, 0);
        // fused inverted attention (logits + softmax + P@V)
        attn_fused_kernel<<<dim3(BB, NCHUNK), 256>>>(qp, kb, vb2, lpart, upart);
        upd_reduce_kernel<<<SROWS, 128>>>(upart, lpart, upd);
        // GRU gates (one launch for both)
        gemm_small_kernel<<<dim3(22, 24, 2), 128>>>(
            upd, cur, W_ih, W_hh, b_ih, b_hh, gi, gh,
            3 * DD, DD, 1, 1.f, 0);
        gru_kernel<<<(SROWS * DD + 255) / 256, 256>>>(gi, gh, cur, stmp);
        // MLP (no residual)
        rowln_kernel<<<SROWS, 256>>>(stmp, ln_m_g, ln_m_b, lnb);
        gemm_small_kernel<<<dim3(22, 32, 1), 128>>>(
            lnb, lnb, W1, W1, b1, b1, h1, h1,
            MLPD, DD, 0, 1.f, 1);
        float* nxt = (it == 2) ? out : (it == 0 ? sA : sB);
        gemm_small_kernel<<<dim3(22, 8, 1), 128>>>(
            h1, h1, W2, W2, b2, b2, nxt, nxt,
            DD, MLPD, 0, 1.f, 0);
        cur = nxt;
    }
}

// round 17
// speedup vs baseline: 2.2454x; 1.3900x over previous
#include <cuda_runtime.h>
#include <cuda_bf16.h>
#include <math.h>
#include <stdint.h>

// ---------------- Problem constants ----------------
#define BB 32
#define SS 11
#define NN 4096
#define DD 512
#define MLPD 2048
#define MROWS (BB*NN)          // 131072
#define SROWS (BB*SS)          // 352
#define NCHUNK 16              // n-chunks per batch (4096/256)
#define EPS_LN 1e-5f
#define EPS_ATTN 1e-8f

// ---------------- Scratch (device globals; no allocation allowed) ----------------
__device__ __nv_bfloat16 g_xlnb[MROWS*DD];   // normalized inputs (bf16)
__device__ __nv_bfloat16 g_kb[MROWS*DD];     // K (bf16)
__device__ __nv_bfloat16 g_vb[MROWS*DD];     // V (bf16)
__device__ __nv_bfloat16 g_wkb[DD*DD];       // Wk^T [n][k] bf16
__device__ __nv_bfloat16 g_wvb[DD*DD];       // Wv^T [n][k] bf16
// split weights: hi at [0, N*K), lo at [N*K, 2*N*K)
__device__ __nv_bfloat16 g_wqb[2*DD*DD];     // Wq^T split
__device__ __nv_bfloat16 g_w1b[2*MLPD*DD];   // W1^T split
__device__ __nv_bfloat16 g_w2b[2*DD*MLPD];   // W2^T split
__device__ __nv_bfloat16 g_wihb[2*3*DD*DD];  // W_ih split ([n][k] already)
__device__ __nv_bfloat16 g_whhb[2*3*DD*DD];  // W_hh split
__device__ float g_q[SROWS*DD];
__device__ float g_lpart[BB*NCHUNK*16];
__device__ float g_upart[BB*NCHUNK*SS*DD];
__device__ float g_upd[SROWS*DD];
__device__ float g_gi[SROWS*3*DD];
__device__ float g_gh[SROWS*3*DD];
__device__ float g_stmp[SROWS*DD];
__device__ float g_sA[SROWS*DD];
__device__ float g_sB[SROWS*DD];
__device__ float g_lnb[SROWS*DD];
__device__ float g_h1[SROWS*MLPD];

__device__ __forceinline__ void bf16_split(float v, __nv_bfloat16& hi, __nv_bfloat16& lo) {
    hi = __float2bfloat16(v);
    lo = __float2bfloat16(v - __bfloat162float(hi));
}

// ---------------- W transpose + bf16 convert (plain, for kv weights) --------------
__global__ void wtrans_any_kernel(const float* __restrict__ src,
                                  __nv_bfloat16* __restrict__ dst, int K, int N)
{
    __shared__ float tile[32][33];
    int k0 = blockIdx.x * 32, n0 = blockIdx.y * 32;
    int tx = threadIdx.x, ty = threadIdx.y;
    tile[ty][tx] = src[(size_t)(k0 + ty) * N + n0 + tx];
    __syncthreads();
    dst[(size_t)(n0 + ty) * K + k0 + tx] = __float2bfloat16(tile[tx][ty]);
}

// ---------------- W transpose + SPLIT convert: src[K][N] -> hi/lo [N][K] ----------
__global__ void wtrans_split_kernel(const float* __restrict__ src,
                                    __nv_bfloat16* __restrict__ dst, int K, int N)
{
    __shared__ float tile[32][33];
    int k0 = blockIdx.x * 32, n0 = blockIdx.y * 32;
    int tx = threadIdx.x, ty = threadIdx.y;
    tile[ty][tx] = src[(size_t)(k0 + ty) * N + n0 + tx];
    __syncthreads();
    float v = tile[tx][ty];
    __nv_bfloat16 hi, lo;
    bf16_split(v, hi, lo);
    size_t idx = (size_t)(n0 + ty) * K + k0 + tx;
    dst[idx] = hi;
    dst[(size_t)N * K + idx] = lo;
}

// ---------------- straight SPLIT convert (weights already [n][k]) ----------------
__global__ void wconv_split_kernel(const float* __restrict__ src,
                                   __nv_bfloat16* __restrict__ dst, int n)
{
    int i = blockIdx.x * 256 + threadIdx.x;
    if (i < n) {
        __nv_bfloat16 hi, lo;
        bf16_split(src[i], hi, lo);
        dst[i] = hi;
        dst[n + i] = lo;
    }
}

// ---------------- warp-per-row LayerNorm -> bf16 (inputs) ----------------
__global__ void __launch_bounds__(256) rowln_bf16_kernel(
    const float* __restrict__ X, const float* __restrict__ g,
    const float* __restrict__ b, __nv_bfloat16* __restrict__ out)
{
    int row = blockIdx.x * 8 + (threadIdx.x >> 5);
    int lane = threadIdx.x & 31;
    const float4* x4 = (const float4*)(X + (size_t)row * DD);
    const float4* g4 = (const float4*)g;
    const float4* b4 = (const float4*)b;
    float4 v[4];
    float s = 0.f, sq = 0.f;
    #pragma unroll
    for (int i = 0; i < 4; i++) {
        v[i] = x4[lane * 4 + i];
        s  += v[i].x + v[i].y + v[i].z + v[i].w;
        sq += v[i].x * v[i].x + v[i].y * v[i].y + v[i].z * v[i].z + v[i].w * v[i].w;
    }
    #pragma unroll
    for (int o = 16; o; o >>= 1) {
        s  += __shfl_xor_sync(0xffffffffu, s, o);
        sq += __shfl_xor_sync(0xffffffffu, sq, o);
    }
    float mu = s * (1.f / DD);
    float rs = rsqrtf(sq * (1.f / DD) - mu * mu + EPS_LN);
    uint4* o4 = (uint4*)(out + (size_t)row * DD);
    #pragma unroll
    for (int i = 0; i < 4; i += 2) {
        uint4 pk;
        uint32_t* pw = (uint32_t*)&pk;
        #pragma unroll
        for (int j = 0; j < 2; j++) {
            float4 gg = g4[lane * 4 + i + j];
            float4 bb = b4[lane * 4 + i + j];
            float4 vv = v[i + j];
            float o0 = (vv.x - mu) * rs * gg.x + bb.x;
            float o1 = (vv.y - mu) * rs * gg.y + bb.y;
            float o2 = (vv.z - mu) * rs * gg.z + bb.z;
            float o3 = (vv.w - mu) * rs * gg.w + bb.w;
            __nv_bfloat162 h0 = __floats2bfloat162_rn(o0, o1);
            __nv_bfloat162 h1 = __floats2bfloat162_rn(o2, o3);
            pw[j * 2]     = *(uint32_t*)&h0;
            pw[j * 2 + 1] = *(uint32_t*)&h1;
        }
        o4[lane * 2 + (i >> 1)] = pk;
    }
}

// ---------------- warp-per-row LayerNorm fp32 (slots) ----------------
__global__ void __launch_bounds__(256) rowln_kernel(
    const float* __restrict__ X, const float* __restrict__ g,
    const float* __restrict__ b, float* __restrict__ out)
{
    int row = blockIdx.x * 8 + (threadIdx.x >> 5);
    int lane = threadIdx.x & 31;
    const float4* x4 = (const float4*)(X + (size_t)row * DD);
    const float4* g4 = (const float4*)g;
    const float4* b4 = (const float4*)b;
    float4 v[4];
    float s = 0.f, sq = 0.f;
    #pragma unroll
    for (int i = 0; i < 4; i++) {
        v[i] = x4[lane * 4 + i];
        s  += v[i].x + v[i].y + v[i].z + v[i].w;
        sq += v[i].x * v[i].x + v[i].y * v[i].y + v[i].z * v[i].z + v[i].w * v[i].w;
    }
    #pragma unroll
    for (int o = 16; o; o >>= 1) {
        s  += __shfl_xor_sync(0xffffffffu, s, o);
        sq += __shfl_xor_sync(0xffffffffu, sq, o);
    }
    float mu = s * (1.f / DD);
    float rs = rsqrtf(sq * (1.f / DD) - mu * mu + EPS_LN);
    float4* o4 = (float4*)(out + (size_t)row * DD);
    #pragma unroll
    for (int i = 0; i < 4; i++) {
        float4 gg = g4[lane * 4 + i];
        float4 bb = b4[lane * 4 + i];
        float4 ov;
        ov.x = (v[i].x - mu) * rs * gg.x + bb.x;
        ov.y = (v[i].y - mu) * rs * gg.y + bb.y;
        ov.z = (v[i].z - mu) * rs * gg.z + bb.z;
        ov.w = (v[i].w - mu) * rs * gg.w + bb.w;
        o4[lane * 4 + i] = ov;
    }
}

// ---------------- bf16 TC GEMM w/ 3-stage cp.async ring (kv) --------------------
__global__ void __launch_bounds__(256) kv_gemm_bf16_kernel(
    const __nv_bfloat16* __restrict__ A,
    const __nv_bfloat16* __restrict__ Wkb, const __nv_bfloat16* __restrict__ Wvb,
    const float* __restrict__ bk, const float* __restrict__ bv,
    __nv_bfloat16* __restrict__ Kout, __nv_bfloat16* __restrict__ Vout)
{
    __shared__ __align__(16) uint32_t As32[3][128][20];
    __shared__ __align__(16) uint32_t Bs32[3][128][20];
    int by = blockIdx.x;
    int m0 = blockIdx.y * 128;
    const __nv_bfloat16* W; const float* bias; __nv_bfloat16* Dst; int cb;
    if (by < 4) { W = Wkb; bias = bk; Dst = Kout; cb = by * 128; }
    else        { W = Wvb; bias = bv; Dst = Vout; cb = (by - 4) * 128; }

    int t = threadIdx.x;
    int warp = t >> 5, lane = t & 31;
    int wm = (warp & 1) * 64;
    int wn = (warp >> 1) * 32;
    int g = lane >> 2, t4 = lane & 3;

    const uint4* A4 = (const uint4*)A;
    const uint4* W4 = (const uint4*)W;

    float c[4][4][4];
    #pragma unroll
    for (int i = 0; i < 4; i++)
        #pragma unroll
        for (int j = 0; j < 4; j++)
            #pragma unroll
            for (int r = 0; r < 4; r++) c[i][j][r] = 0.f;

#define KV_LOAD(st, kk0) do {                                                   \
        _Pragma("unroll")                                                       \
        for (int i = 0; i < 2; i++) {                                           \
            int item = t + i * 256;                                             \
            int rm = item >> 2, aq = item & 3;                                  \
            const uint4* ga = A4 + (size_t)(m0 + rm) * 64 + ((kk0) >> 3) + aq;  \
            uint32_t sa = (uint32_t)__cvta_generic_to_shared(&As32[st][rm][aq*4]);\
            asm volatile("cp.async.cg.shared.global [%0], [%1], 16;\n"          \
                         :: "r"(sa), "l"(ga));                                  \
            const uint4* gb = W4 + (size_t)(cb + rm) * 64 + ((kk0) >> 3) + aq;  \
            uint32_t sb = (uint32_t)__cvta_generic_to_shared(&Bs32[st][rm][aq*4]);\
            asm volatile("cp.async.cg.shared.global [%0], [%1], 16;\n"          \
                         :: "r"(sb), "l"(gb));                                  \
        }                                                                       \
    } while (0)

    KV_LOAD(0, 0);
    asm volatile("cp.async.commit_group;\n");
    KV_LOAD(1, 32);
    asm volatile("cp.async.commit_group;\n");

    #pragma unroll 1
    for (int it = 0; it < 16; it++) {
        int st = it % 3;
        if (it < 15) asm volatile("cp.async.wait_group 1;\n");
        else         asm volatile("cp.async.wait_group 0;\n");
        __syncthreads();
        if (it + 2 < 16) {
            int pst = (it + 2) % 3;
            KV_LOAD(pst, (it + 2) * 32);
            asm volatile("cp.async.commit_group;\n");
        }

        #pragma unroll
        for (int ks = 0; ks < 2; ks++) {
            int kb2 = ks * 8;
            uint32_t a[4][4], bf[4][2];
            #pragma unroll
            for (int i = 0; i < 4; i++) {
                int mb = wm + i * 16;
                a[i][0] = As32[st][mb + g][kb2 + t4];
                a[i][1] = As32[st][mb + g + 8][kb2 + t4];
                a[i][2] = As32[st][mb + g][kb2 + t4 + 4];
                a[i][3] = As32[st][mb + g + 8][kb2 + t4 + 4];
            }
            #pragma unroll
            for (int j = 0; j < 4; j++) {
                int nb = wn + j * 8;
                bf[j][0] = Bs32[st][nb + g][kb2 + t4];
                bf[j][1] = Bs32[st][nb + g][kb2 + t4 + 4];
            }
            #pragma unroll
            for (int i = 0; i < 4; i++)
                #pragma unroll
                for (int j = 0; j < 4; j++) {
                    asm volatile(
                        "mma.sync.aligned.m16n8k16.row.col.f32.bf16.bf16.f32 "
                        "{%0,%1,%2,%3}, {%4,%5,%6,%7}, {%8,%9}, {%0,%1,%2,%3};\n"
                        : "+f"(c[i][j][0]), "+f"(c[i][j][1]),
                          "+f"(c[i][j][2]), "+f"(c[i][j][3])
                        : "r"(a[i][0]), "r"(a[i][1]), "r"(a[i][2]), "r"(a[i][3]),
                          "r"(bf[j][0]), "r"(bf[j][1]));
                }
        }
    }
#undef KV_LOAD

    uint32_t* D32 = (uint32_t*)Dst;
    #pragma unroll
    for (int i = 0; i < 4; i++) {
        int row = m0 + wm + i * 16 + g;
        #pragma unroll
        for (int j = 0; j < 4; j++) {
            int col = wn + j * 8 + t4 * 2;
            float bx = bias[cb + col], by2 = bias[cb + col + 1];
            int c2 = ((cb + col) >> 1);
            __nv_bfloat162 v0 = __floats2bfloat162_rn(c[i][j][0] + bx, c[i][j][1] + by2);
            __nv_bfloat162 v1 = __floats2bfloat162_rn(c[i][j][2] + bx, c[i][j][3] + by2);
            D32[(size_t)row * 256 + c2] = *(uint32_t*)&v0;
            D32[(size_t)(row + 8) * 256 + c2] = *(uint32_t*)&v1;
        }
    }
}

// ----- bf16x3 TC small GEMM: C = scale*(A_f32 @ B_split^T) + bias, opt relu -------
// Split precision: A -> (ah, al) on the fly; B stored (hi, lo) with lo at B + N*K.
// acc = ah*bh + ah*bl + al*bh  (error ~ eps_bf16^2, fp32-class).
// Block 32x64, 128 threads (4 warps, each m32 x n16). One __syncthreads per k-tile.
__global__ void __launch_bounds__(128) gemm_tc3_kernel(
    const float* __restrict__ A0, const float* __restrict__ A1,
    const __nv_bfloat16* __restrict__ B0, const __nv_bfloat16* __restrict__ B1,
    const float* __restrict__ bias0, const float* __restrict__ bias1,
    float* __restrict__ C0, float* __restrict__ C1,
    int N, int K, float scale, int relu)
{
    const float* A = blockIdx.z ? A1 : A0;
    const __nv_bfloat16* Bm = blockIdx.z ? B1 : B0;
    const float* bias = blockIdx.z ? bias1 : bias0;
    float* C = blockIdx.z ? C1 : C0;

    __shared__ __align__(16) uint32_t As32[2][2][32][20];   // [stage][hi/lo][m][k2]
    __shared__ __align__(16) uint32_t Bs32[3][2][64][20];   // [stage][hi/lo][n][k2]
    int m0 = blockIdx.x * 32, n0 = blockIdx.y * 64;
    int t = threadIdx.x;
    int warp = t >> 5, lane = t & 31;
    int g = lane >> 2, t4 = lane & 3;
    const uint4* B4 = (const uint4*)Bm;
    size_t loOff4 = ((size_t)N * K) >> 3;     // lo half offset in uint4 units
    int Kq = K >> 3;
    int T = K >> 5;

    float c[2][2][4];
    #pragma unroll
    for (int i = 0; i < 2; i++)
        #pragma unroll
        for (int j = 0; j < 2; j++)
            #pragma unroll
            for (int r = 0; r < 4; r++) c[i][j][r] = 0.f;

    float2 aR[4];
#define LDA(kt) do {                                                             \
        _Pragma("unroll")                                                        \
        for (int i = 0; i < 4; i++) {                                            \
            int item = t + i * 128;                                              \
            int m = item >> 4, k2 = item & 15;                                   \
            aR[i] = *(const float2*)(A + (size_t)(m0 + m) * K + (kt) * 32 + k2 * 2); \
        }                                                                        \
    } while (0)
#define STA(st) do {                                                             \
        _Pragma("unroll")                                                        \
        for (int i = 0; i < 4; i++) {                                            \
            int item = t + i * 128;                                              \
            int m = item >> 4, k2 = item & 15;                                   \
            __nv_bfloat16 hx, lx, hy, ly;                                        \
            bf16_split(aR[i].x, hx, lx);                                         \
            bf16_split(aR[i].y, hy, ly);                                         \
            __nv_bfloat162 hh = __halves2bfloat162(hx, hy);                      \
            __nv_bfloat162 ll = __halves2bfloat162(lx, ly);                      \
            As32[st][0][m][k2] = *(uint32_t*)&hh;                                \
            As32[st][1][m][k2] = *(uint32_t*)&ll;                                \
        }                                                                        \
    } while (0)
#define CPB(st, kt) do {                                                         \
        _Pragma("unroll")                                                        \
        for (int h = 0; h < 2; h++) {                                            \
            _Pragma("unroll")                                                    \
            for (int i = 0; i < 2; i++) {                                        \
                int item = t + i * 128;                                          \
                int n = item >> 2, q = item & 3;                                 \
                const uint4* gb = B4 + h * loOff4 + (size_t)(n0 + n) * Kq + (kt) * 4 + q; \
                uint32_t sb = (uint32_t)__cvta_generic_to_shared(&Bs32[st][h][n][q*4]); \
                asm volatile("cp.async.cg.shared.global [%0], [%1], 16;\n"       \
                             :: "r"(sb), "l"(gb));                               \
            }                                                                    \
        }                                                                        \
    } while (0)

    LDA(0);
    CPB(0, 0);
    asm volatile("cp.async.commit_group;\n");
    CPB(1, 1);
    asm volatile("cp.async.commit_group;\n");

    #pragma unroll 1
    for (int it = 0; it < T; it++) {
        int aCur = it & 1, bCur = it % 3;
        STA(aCur);
        if (it + 1 < T) LDA(it + 1);
        if (it < T - 1) asm volatile("cp.async.wait_group 1;\n");
        else            asm volatile("cp.async.wait_group 0;\n");
        __syncthreads();
        if (it + 2 < T) {
            CPB((it + 2) % 3, it + 2);
            asm volatile("cp.async.commit_group;\n");
        }

        #pragma unroll
        for (int ks = 0; ks < 2; ks++) {
            int kb2 = ks * 8;
            uint32_t ah[2][4], al[2][4];
            #pragma unroll
            for (int mi = 0; mi < 2; mi++) {
                int mb = mi * 16;
                ah[mi][0] = As32[aCur][0][mb + g][kb2 + t4];
                ah[mi][1] = As32[aCur][0][mb + g + 8][kb2 + t4];
                ah[mi][2] = As32[aCur][0][mb + g][kb2 + t4 + 4];
                ah[mi][3] = As32[aCur][0][mb + g + 8][kb2 + t4 + 4];
                al[mi][0] = As32[aCur][1][mb + g][kb2 + t4];
                al[mi][1] = As32[aCur][1][mb + g + 8][kb2 + t4];
                al[mi][2] = As32[aCur][1][mb + g][kb2 + t4 + 4];
                al[mi][3] = As32[aCur][1][mb + g + 8][kb2 + t4 + 4];
            }
            #pragma unroll
            for (int nj = 0; nj < 2; nj++) {
                int nb = warp * 16 + nj * 8;
                uint32_t bh0 = Bs32[bCur][0][nb + g][kb2 + t4];
                uint32_t bh1 = Bs32[bCur][0][nb + g][kb2 + t4 + 4];
                uint32_t bl0 = Bs32[bCur][1][nb + g][kb2 + t4];
                uint32_t bl1 = Bs32[bCur][1][nb + g][kb2 + t4 + 4];
                #pragma unroll
                for (int mi = 0; mi < 2; mi++) {
                    asm volatile(
                        "mma.sync.aligned.m16n8k16.row.col.f32.bf16.bf16.f32 "
                        "{%0,%1,%2,%3}, {%4,%5,%6,%7}, {%8,%9}, {%0,%1,%2,%3};\n"
                        : "+f"(c[mi][nj][0]), "+f"(c[mi][nj][1]),
                          "+f"(c[mi][nj][2]), "+f"(c[mi][nj][3])
                        : "r"(ah[mi][0]), "r"(ah[mi][1]), "r"(ah[mi][2]), "r"(ah[mi][3]),
                          "r"(bl0), "r"(bl1));
                    asm volatile(
                        "mma.sync.aligned.m16n8k16.row.col.f32.bf16.bf16.f32 "
                        "{%0,%1,%2,%3}, {%4,%5,%6,%7}, {%8,%9}, {%0,%1,%2,%3};\n"
                        : "+f"(c[mi][nj][0]), "+f"(c[mi][nj][1]),
                          "+f"(c[mi][nj][2]), "+f"(c[mi][nj][3])
                        : "r"(al[mi][0]), "r"(al[mi][1]), "r"(al[mi][2]), "r"(al[mi][3]),
                          "r"(bh0), "r"(bh1));
                    asm volatile(
                        "mma.sync.aligned.m16n8k16.row.col.f32.bf16.bf16.f32 "
                        "{%0,%1,%2,%3}, {%4,%5,%6,%7}, {%8,%9}, {%0,%1,%2,%3};\n"
                        : "+f"(c[mi][nj][0]), "+f"(c[mi][nj][1]),
                          "+f"(c[mi][nj][2]), "+f"(c[mi][nj][3])
                        : "r"(ah[mi][0]), "r"(ah[mi][1]), "r"(ah[mi][2]), "r"(ah[mi][3]),
                          "r"(bh0), "r"(bh1));
                }
            }
        }
    }
#undef LDA
#undef STA
#undef CPB

    #pragma unroll
    for (int mi = 0; mi < 2; mi++) {
        int row = m0 + mi * 16 + g;
        #pragma unroll
        for (int nj = 0; nj < 2; nj++) {
            int col = n0 + warp * 16 + nj * 8 + t4 * 2;
            float bx = 0.f, by2 = 0.f;
            if (bias) { bx = bias[col]; by2 = bias[col + 1]; }
            float2 v0 = make_float2(c[mi][nj][0] * scale + bx, c[mi][nj][1] * scale + by2);
            float2 v1 = make_float2(c[mi][nj][2] * scale + bx, c[mi][nj][3] * scale + by2);
            if (relu) {
                v0.x = fmaxf(v0.x, 0.f); v0.y = fmaxf(v0.y, 0.f);
                v1.x = fmaxf(v1.x, 0.f); v1.y = fmaxf(v1.y, 0.f);
            }
            *(float2*)(C + (size_t)row * N + col) = v0;
            *(float2*)(C + (size_t)(row + 8) * N + col) = v1;
        }
    }
}

// ------- Fused attention: TC logits + softmax(over S) + P@V, one kernel ---------
__global__ void __launch_bounds__(256) attn_fused_kernel(
    const float* __restrict__ q, const __nv_bfloat16* __restrict__ Kb,
    const __nv_bfloat16* __restrict__ Vb,
    float* __restrict__ lpart, float* __restrict__ upart)
{
    __shared__ __align__(16) uint32_t Qs32[16][20];
    __shared__ __align__(16) uint32_t Ks32[256][20];
    __shared__ __align__(16) float StT[256][20];
    __shared__ float wsum[8][12];
    int b = blockIdx.x, chunk = blockIdx.y;
    int t = threadIdx.x;
    int warp = t >> 5, lane = t & 31;
    int g = lane >> 2, t4 = lane & 3;
    int n0 = chunk * 256;
    const uint4* kb4 = (const uint4*)(Kb + ((size_t)b * NN + n0) * DD);

    float c[4][4];
    #pragma unroll
    for (int j = 0; j < 4; j++)
        #pragma unroll
        for (int r = 0; r < 4; r++) c[j][r] = 0.f;

    for (int k0 = 0; k0 < DD; k0 += 32) {
        {
            int s = t >> 4, k2 = t & 15;
            float2 f = make_float2(0.f, 0.f);
            if (s < SS) f = *(const float2*)(q + (size_t)(b * SS + s) * DD + k0 + k2 * 2);
            __nv_bfloat162 h = __floats2bfloat162_rn(f.x, f.y);
            Qs32[s][k2] = *(uint32_t*)&h;
        }
        #pragma unroll
        for (int i = 0; i < 4; i++) {
            int item = t + i * 256;
            int n = item >> 2, aq = item & 3;
            uint4 v = kb4[(size_t)n * 64 + (k0 >> 3) + aq];
            *(uint4*)&Ks32[n][aq * 4] = v;
        }
        __syncthreads();
        #pragma unroll
        for (int ks = 0; ks < 2; ks++) {
            int kb2 = ks * 8;
            uint32_t a[4];
            a[0] = Qs32[g][kb2 + t4];
            a[1] = Qs32[g + 8][kb2 + t4];
            a[2] = Qs32[g][kb2 + t4 + 4];
            a[3] = Qs32[g + 8][kb2 + t4 + 4];
            #pragma unroll
            for (int j = 0; j < 4; j++) {
                int nb = warp * 32 + j * 8;
                uint32_t b0 = Ks32[nb + g][kb2 + t4];
                uint32_t b1 = Ks32[nb + g][kb2 + t4 + 4];
                asm volatile(
                    "mma.sync.aligned.m16n8k16.row.col.f32.bf16.bf16.f32 "
                    "{%0,%1,%2,%3}, {%4,%5,%6,%7}, {%8,%9}, {%0,%1,%2,%3};\n"
                    : "+f"(c[j][0]), "+f"(c[j][1]), "+f"(c[j][2]), "+f"(c[j][3])
                    : "r"(a[0]), "r"(a[1]), "r"(a[2]), "r"(a[3]),
                      "r"(b0), "r"(b1));
            }
        }
        __syncthreads();
    }

    #pragma unroll
    for (int j = 0; j < 4; j++) {
        int nn = warp * 32 + j * 8 + t4 * 2;
        StT[nn][g]         = c[j][0];
        StT[nn + 1][g]     = c[j][1];
        StT[nn][g + 8]     = c[j][2];
        StT[nn + 1][g + 8] = c[j][3];
    }
    __syncthreads();

    float p[SS];
    {
        float4 l0 = *(const float4*)&StT[t][0];
        float4 l1 = *(const float4*)&StT[t][4];
        float4 l2 = *(const float4*)&StT[t][8];
        p[0]=l0.x; p[1]=l0.y; p[2]=l0.z; p[3]=l0.w;
        p[4]=l1.x; p[5]=l1.y; p[6]=l1.z; p[7]=l1.w;
        p[8]=l2.x; p[9]=l2.y; p[10]=l2.z;
        float m = -1e30f;
        #pragma unroll
        for (int s = 0; s < SS; s++) m = fmaxf(m, p[s]);
        float sum = 0.f;
        #pragma unroll
        for (int s = 0; s < SS; s++) { p[s] = __expf(p[s] - m); sum += p[s]; }
        float r = 1.f / sum;
        #pragma unroll
        for (int s = 0; s < SS; s++) p[s] *= r;
    }
    #pragma unroll
    for (int s = 0; s < SS; s++) {
        float v = p[s];
        #pragma unroll
        for (int o = 16; o; o >>= 1) v += __shfl_xor_sync(0xffffffffu, v, o);
        if (lane == 0) wsum[warp][s] = v;
    }
    *(float4*)&StT[t][0] = make_float4(p[0], p[1], p[2], p[3]);
    *(float4*)&StT[t][4] = make_float4(p[4], p[5], p[6], p[7]);
    *(float4*)&StT[t][8] = make_float4(p[8], p[9], p[10], 0.f);
    __syncthreads();
    if (t < SS) {
        float v = 0.f;
        #pragma unroll
        for (int w = 0; w < 8; w++) v += wsum[w][t];
        lpart[(b * NCHUNK + chunk) * 16 + t] = v;
    }

    const __nv_bfloat16* vb = Vb + (size_t)b * NN * DD;
    float acc[SS][2];
    #pragma unroll
    for (int s = 0; s < SS; s++) { acc[s][0] = 0.f; acc[s][1] = 0.f; }
    for (int n = 0; n < 256; n++) {
        uint32_t raw = *(const uint32_t*)(vb + (size_t)(n0 + n) * DD + 2 * t);
        float2 v = __bfloat1622float2(*(__nv_bfloat162*)&raw);
        float4 p0 = *(const float4*)&StT[n][0];
        float4 p1 = *(const float4*)&StT[n][4];
        float4 p2 = *(const float4*)&StT[n][8];
        acc[0][0]  = fmaf(p0.x, v.x, acc[0][0]);  acc[0][1]  = fmaf(p0.x, v.y, acc[0][1]);
        acc[1][0]  = fmaf(p0.y, v.x, acc[1][0]);  acc[1][1]  = fmaf(p0.y, v.y, acc[1][1]);
        acc[2][0]  = fmaf(p0.z, v.x, acc[2][0]);  acc[2][1]  = fmaf(p0.z, v.y, acc[2][1]);
        acc[3][0]  = fmaf(p0.w, v.x, acc[3][0]);  acc[3][1]  = fmaf(p0.w, v.y, acc[3][1]);
        acc[4][0]  = fmaf(p1.x, v.x, acc[4][0]);  acc[4][1]  = fmaf(p1.x, v.y, acc[4][1]);
        acc[5][0]  = fmaf(p1.y, v.x, acc[5][0]);  acc[5][1]  = fmaf(p1.y, v.y, acc[5][1]);
        acc[6][0]  = fmaf(p1.z, v.x, acc[6][0]);  acc[6][1]  = fmaf(p1.z, v.y, acc[6][1]);
        acc[7][0]  = fmaf(p1.w, v.x, acc[7][0]);  acc[7][1]  = fmaf(p1.w, v.y, acc[7][1]);
        acc[8][0]  = fmaf(p2.x, v.x, acc[8][0]);  acc[8][1]  = fmaf(p2.x, v.y, acc[8][1]);
        acc[9][0]  = fmaf(p2.y, v.x, acc[9][0]);  acc[9][1]  = fmaf(p2.y, v.y, acc[9][1]);
        acc[10][0] = fmaf(p2.z, v.x, acc[10][0]); acc[10][1] = fmaf(p2.z, v.y, acc[10][1]);
    }
    #pragma unroll
    for (int s = 0; s < SS; s++) {
        float2 o = make_float2(acc[s][0], acc[s][1]);
        *(float2*)(upart + ((size_t)((b * NCHUNK + chunk) * SS + s)) * DD + 2 * t) = o;
    }
}

// ---------------- reduce partials + inv inline ----------------
__global__ void __launch_bounds__(128) upd_reduce_kernel(
    const float* __restrict__ upart, const float* __restrict__ lpart,
    float* __restrict__ upd)
{
    int row = blockIdx.x;
    int b = row / SS, s = row % SS;
    int t = threadIdx.x;
    float sum = 0.f;
    #pragma unroll
    for (int c = 0; c < NCHUNK; c++) sum += lpart[(b * NCHUNK + c) * 16 + s];
    float iv = 1.f / (sum + EPS_ATTN);
    float4 acc = make_float4(0.f, 0.f, 0.f, 0.f);
    for (int c = 0; c < NCHUNK; c++) {
        float4 v = *(const float4*)(upart + ((size_t)((b * NCHUNK + c) * SS + s)) * DD + t * 4);
        acc.x += v.x; acc.y += v.y; acc.z += v.z; acc.w += v.w;
    }
    acc.x *= iv; acc.y *= iv; acc.z *= iv; acc.w *= iv;
    *(float4*)(upd + (size_t)row * DD + t * 4) = acc;
}

// ---------------- GRU elementwise ----------------
__global__ void __launch_bounds__(256) gru_kernel(
    const float* __restrict__ gi, const float* __restrict__ gh,
    const float* __restrict__ slots, float* __restrict__ out)
{
    int idx = blockIdx.x * 256 + threadIdx.x;
    if (idx >= SROWS * DD) return;
    int row = idx >> 9, d = idx & 511;
    size_t base = (size_t)row * (3 * DD);
    float ir = gi[base + d], iz = gi[base + DD + d], inn = gi[base + 2 * DD + d];
    float hr = gh[base + d], hz = gh[base + DD + d], hn = gh[base + 2 * DD + d];
    float r = 1.f / (1.f + __expf(-(ir + hr)));
    float z = 1.f / (1.f + __expf(-(iz + hz)));
    float nn = tanhf(inn + r * hn);
    out[idx] = (1.f - z) * nn + z * slots[idx];
}

// ---------------- Host orchestration ----------------
extern "C" void kernel_launch(void* const* d_in, const int* in_sizes, int n_in,
                              void* d_out, int out_size)
{
    const float* slots0  = (const float*)d_in[0];
    const float* inputs  = (const float*)d_in[1];
    const float* ln_in_g = (const float*)d_in[2];
    const float* ln_in_b = (const float*)d_in[3];
    const float* Wk      = (const float*)d_in[4];
    const float* bk      = (const float*)d_in[5];
    const float* Wv      = (const float*)d_in[6];
    const float* bv      = (const float*)d_in[7];
    const float* ln_q_g  = (const float*)d_in[8];
    const float* ln_q_b  = (const float*)d_in[9];
    const float* Wq      = (const float*)d_in[10];
    const float* W_ih    = (const float*)d_in[11];
    const float* b_ih    = (const float*)d_in[12];
    const float* W_hh    = (const float*)d_in[13];
    const float* b_hh    = (const float*)d_in[14];
    const float* ln_m_g  = (const float*)d_in[15];
    const float* ln_m_b  = (const float*)d_in[16];
    const float* W1      = (const float*)d_in[17];
    const float* b1      = (const float*)d_in[18];
    const float* W2      = (const float*)d_in[19];
    const float* b2      = (const float*)d_in[20];
    float* out = (float*)d_out;

    __nv_bfloat16 *xlnb, *kb, *vb2, *wkb, *wvb, *wqb, *w1b, *w2b, *wihb, *whhb;
    float *qp, *lpart, *upart, *upd, *gi, *gh;
    float *stmp, *sA, *sB, *lnb, *h1;
    cudaGetSymbolAddress((void**)&xlnb, g_xlnb);
    cudaGetSymbolAddress((void**)&kb,   g_kb);
    cudaGetSymbolAddress((void**)&vb2,  g_vb);
    cudaGetSymbolAddress((void**)&wkb,  g_wkb);
    cudaGetSymbolAddress((void**)&wvb,  g_wvb);
    cudaGetSymbolAddress((void**)&wqb,  g_wqb);
    cudaGetSymbolAddress((void**)&w1b,  g_w1b);
    cudaGetSymbolAddress((void**)&w2b,  g_w2b);
    cudaGetSymbolAddress((void**)&wihb, g_wihb);
    cudaGetSymbolAddress((void**)&whhb, g_whhb);
    cudaGetSymbolAddress((void**)&qp,   g_q);
    cudaGetSymbolAddress((void**)&lpart,g_lpart);
    cudaGetSymbolAddress((void**)&upart,g_upart);
    cudaGetSymbolAddress((void**)&upd,  g_upd);
    cudaGetSymbolAddress((void**)&gi,   g_gi);
    cudaGetSymbolAddress((void**)&gh,   g_gh);
    cudaGetSymbolAddress((void**)&stmp, g_stmp);
    cudaGetSymbolAddress((void**)&sA,   g_sA);
    cudaGetSymbolAddress((void**)&sB,   g_sB);
    cudaGetSymbolAddress((void**)&lnb,  g_lnb);
    cudaGetSymbolAddress((void**)&h1,   g_h1);

    const float qscale = 0.044194173824159216f; // 1/sqrt(512)
    dim3 t32(32, 32);

    // one-time: weight conversions (kv plain bf16; small-GEMM weights split hi/lo)
    wtrans_any_kernel<<<dim3(16, 16), t32>>>(Wk, wkb, DD, DD);
    wtrans_any_kernel<<<dim3(16, 16), t32>>>(Wv, wvb, DD, DD);
    wtrans_split_kernel<<<dim3(16, 16), t32>>>(Wq, wqb, DD, DD);
    wtrans_split_kernel<<<dim3(16, 64), t32>>>(W1, w1b, DD, MLPD);
    wtrans_split_kernel<<<dim3(64, 16), t32>>>(W2, w2b, MLPD, DD);
    wconv_split_kernel<<<(3 * DD * DD + 255) / 256, 256>>>(W_ih, wihb, 3 * DD * DD);
    wconv_split_kernel<<<(3 * DD * DD + 255) / 256, 256>>>(W_hh, whhb, 3 * DD * DD);
    rowln_bf16_kernel<<<MROWS / 8, 256>>>(inputs, ln_in_g, ln_in_b, xlnb);
    kv_gemm_bf16_kernel<<<dim3(8, MROWS / 128), 256>>>(xlnb, wkb, wvb, bk, bv, kb, vb2);

    const float* cur = slots0;
    for (int it = 0; it < 3; it++) {
        // q = LN(slots) @ Wq * scale
        rowln_kernel<<<SROWS / 8, 256>>>(cur, ln_q_g, ln_q_b, lnb);
        gemm_tc3_kernel<<<dim3(11, 8, 1), 128>>>(
            lnb, lnb, wqb, wqb, nullptr, nullptr, qp, qp,
            DD, DD, qscale, 0);
        // fused inverted attention
        attn_fused_kernel<<<dim3(BB, NCHUNK), 256>>>(qp, kb, vb2, lpart, upart);
        upd_reduce_kernel<<<SROWS, 128>>>(upart, lpart, upd);
        // GRU gates (one launch for both)
        gemm_tc3_kernel<<<dim3(11, 24, 2), 128>>>(
            upd, cur, wihb, whhb, b_ih, b_hh, gi, gh,
            3 * DD, DD, 1.f, 0);
        gru_kernel<<<(SROWS * DD + 255) / 256, 256>>>(gi, gh, cur, stmp);
        // MLP (no residual)
        rowln_kernel<<<SROWS / 8, 256>>>(stmp, ln_m_g, ln_m_b, lnb);
        gemm_tc3_kernel<<<dim3(11, 32, 1), 128>>>(
            lnb, lnb, w1b, w1b, b1, b1, h1, h1,
            MLPD, DD, 1.f, 1);
        float* nxt = (it == 2) ? out : (it == 0 ? sA : sB);
        gemm_tc3_kernel<<<dim3(11, 8, 1), 128>>>(
            h1, h1, w2b, w2b, b2, b2, nxt, nxt,
            DD, MLPD, 1.f, 0);
        cur = nxt;
    }
}